// round 10
// baseline (speedup 1.0000x reference)
#include <cuda_runtime.h>
#include <math_constants.h>

#define N_IN   16384
#define NCONV  128
#define KMAX   11
#define TPB    512
#define CPB    16    // convs per block == warps per block

__device__ __forceinline__ float warpReduceMax(float v) {
#pragma unroll
    for (int o = 16; o > 0; o >>= 1)
        v = fmaxf(v, __shfl_xor_sync(0xffffffffu, v, o));
    return v;
}
__device__ __forceinline__ int warpReduceSum(int v) {
#pragma unroll
    for (int o = 16; o > 0; o >>= 1)
        v += __shfl_xor_sync(0xffffffffu, v, o);
    return v;
}

__device__ __forceinline__ int meta_at(const void* arr, int c, bool is64) {
    if (is64) return (int)((const long long*)arr)[c];
    return ((const int*)arr)[c];
}

// ---- ring FIR, no bounds checks. Loads exactly len+K-1 taps.
// Invariant: tap (m0+j) lives at z[j % K]; after `full` groups the oldest
// needed tap is at z[0], so the tail is straight-indexed with a shift reg. ----
template <int K>
__device__ __forceinline__ void ring_fast(
    const float* __restrict__ xs, const float* __restrict__ w, float bias,
    int i0, int d, int len, float& mx, int& neg)
{
    const float* ptr = xs + i0;
    float z[K];
#pragma unroll
    for (int s = 0; s < K - 1; s++) { z[s] = *ptr; ptr += d; }

    const int full = len / K;
    const int rem  = len - full * K;

    for (int g = 0; g < full; g++) {
#pragma unroll
        for (int s = 0; s < K; s++) {
            z[(s + K - 1) % K] = *ptr; ptr += d;   // newest tap
            float y = fmaf(w[0], z[s % K], bias);
#pragma unroll
            for (int t = 1; t < K; t++)
                y = fmaf(w[t], z[(s + t) % K], y);
            mx = fmaxf(mx, y);
            neg += (int)(__float_as_uint(y) >> 31);
        }
    }
    // exact-length tail: oldest tap at z[0], shift register, no predication waste
#pragma unroll 1
    for (int s = 0; s < rem; s++) {
        float nw = *ptr; ptr += d;
        float y = fmaf(w[0], z[0], bias);
#pragma unroll
        for (int t = 1; t < K; t++)
            y = fmaf(w[t], (t < K - 1) ? z[t] : nw, y);
        mx = fmaxf(mx, y);
        neg += (int)(__float_as_uint(y) >> 31);
#pragma unroll
        for (int t = 0; t < K - 2; t++) z[t] = z[t + 1];
        z[K - 2] = nw;
    }
}

// ---- same ring, OOB taps clamped to zero sentinel xs[N_IN] (edges only) ----
template <int K>
__device__ __forceinline__ void ring_clamped(
    const float* __restrict__ xs, const float* __restrict__ w, float bias,
    int i0, int d, int len, float& mx, int& neg)
{
    int ix = i0;
    float z[K];
#pragma unroll
    for (int s = 0; s < K - 1; s++) {
        unsigned ui = min((unsigned)ix, (unsigned)N_IN);
        z[s] = xs[ui]; ix += d;
    }

    const int full = len / K;
    const int rem  = len - full * K;

    for (int g = 0; g < full; g++) {
#pragma unroll
        for (int s = 0; s < K; s++) {
            unsigned ui = min((unsigned)ix, (unsigned)N_IN);
            z[(s + K - 1) % K] = xs[ui]; ix += d;
            float y = fmaf(w[0], z[s % K], bias);
#pragma unroll
            for (int t = 1; t < K; t++)
                y = fmaf(w[t], z[(s + t) % K], y);
            mx = fmaxf(mx, y);
            neg += (int)(__float_as_uint(y) >> 31);
        }
    }
#pragma unroll 1
    for (int s = 0; s < rem; s++) {
        unsigned ui = min((unsigned)ix, (unsigned)N_IN);
        float nw = xs[ui]; ix += d;
        float y = fmaf(w[0], z[0], bias);
#pragma unroll
        for (int t = 1; t < K; t++)
            y = fmaf(w[t], (t < K - 1) ? z[t] : nw, y);
        mx = fmaxf(mx, y);
        neg += (int)(__float_as_uint(y) >> 31);
#pragma unroll
        for (int t = 0; t < K - 2; t++) z[t] = z[t + 1];
        z[K - 2] = nw;
    }
}

// Process segment m in [ma, mb) of phase r, split into
// clamped head [ma, b1) | fast [b1, b2) | clamped tail [b2, mb).
// Fast region: m in [0, f_hi] => all taps r+m*d .. r+(m+K-1)*d in [0, N_IN).
template <int K>
__device__ __forceinline__ void seg3(
    const float* __restrict__ xs, const float* __restrict__ w, float bias,
    int r, int d, int ma, int mb, int f_hi_p1, float& mx, int& neg)
{
    const int b1 = min(mb, max(ma, 0));
    const int b2 = max(b1, min(mb, f_hi_p1));
    if (ma < b1) ring_clamped<K>(xs, w, bias, r + ma * d, d, b1 - ma, mx, neg);
    if (b1 < b2) ring_fast<K>(xs, w, bias, r + b1 * d, d, b2 - b1, mx, neg);
    if (b2 < mb) ring_clamped<K>(xs, w, bias, r + b2 * d, d, mb - b2, mx, neg);
}

// One warp handles one conv. Outputs u = t - p = r + m*d.
template <int K>
__device__ __forceinline__ void conv_feat_warp(
    const float* __restrict__ xs,
    const float* __restrict__ wrow, float bias,
    int d, int p, int L,
    float& mx_out, int& neg_out)
{
    float w[K];
#pragma unroll
    for (int j = 0; j < K; j++) w[j] = wrow[j];

    float mx = -CUDART_INF_F;
    int   neg = 0;
    const int lane = threadIdx.x & 31;

    // Per-conv divides (once per warp):
    //  m_lo(r) = -(pq + (prm + r >= d))          [first valid output of phase r]
    //  m_hi(r) = aq - (r > arm)                  [last valid output]
    //  f_hi(r) = nq - (r > nrm) - (K-1)          [last all-taps-in-range output]
    const int A   = L - 1 - p;
    const int pq  = p / d,          prm = p - pq * d;
    const int aq  = A / d,          arm = A - aq * d;
    const int nq  = (N_IN - 1) / d, nrm = (N_IN - 1) - nq * d;

    if (d >= 32) {
        // lane <-> phase, strided; addresses r == lane (mod 32): conflict-free
        for (int r = lane; r < d; r += 32) {
            const int m_lo = -(pq + ((prm + r) >= d ? 1 : 0));
            const int m_hi = aq - (r > arm ? 1 : 0);
            if (m_hi < m_lo) continue;
            const int f_hi = nq - (r > nrm ? 1 : 0) - (K - 1);
            seg3<K>(xs, w, bias, r, d, m_lo, m_hi + 1, f_hi + 1, mx, neg);
        }
    } else {
        // d phases x nQ chunks of C outputs; C == 1 (mod 32) keeps the 32
        // lane addresses distinct mod 32 at every step.
        const int nQ     = (32 + d - 1) / d;
        const int maxlen = (L + d - 1) / d;
        const int c0     = (maxlen + nQ - 1) / nQ;
        const int C      = (((c0 + 31) >> 5) << 5) | 1;   // >= c0, == 1 mod 32
        const int nItems = d * nQ;
        const float rd   = 1.0f / (float)d;

        for (int j = lane; j < nItems; j += 32) {
            int q = (int)((float)j * rd);
            int r = j - q * d;
            if (r < 0)       { r += d; q--; }
            else if (r >= d) { r -= d; q++; }

            const int m_lo = -(pq + ((prm + r) >= d ? 1 : 0));
            const int m_hi = aq - (r > arm ? 1 : 0);
            const int m0   = m_lo + q * C;
            const int m1   = min(m0 + C, m_hi + 1);
            if (m1 <= m0) continue;
            const int f_hi = nq - (r > nrm ? 1 : 0) - (K - 1);
            seg3<K>(xs, w, bias, r, d, m0, m1, f_hi + 1, mx, neg);
        }
    }

    mx_out = mx;
    neg_out = neg;
}

__global__ void __launch_bounds__(TPB, 2)
feat_kernel(const float* __restrict__ x,
            const float* __restrict__ W,
            const float* __restrict__ B,
            const void* __restrict__ KS,
            const void* __restrict__ DS,
            const void* __restrict__ PS,
            float* __restrict__ out)
{
    extern __shared__ float xs[];   // N_IN + zero sentinel
    const int b = blockIdx.y;

    {
        const float4* xr4 = (const float4*)(x + (size_t)b * N_IN);
        float4* xs4 = (float4*)xs;
        for (int i = threadIdx.x; i < N_IN / 4; i += TPB)
            xs4[i] = xr4[i];
        if (threadIdx.x == 0) xs[N_IN] = 0.0f;
    }
    __syncthreads();

    // int64 vs int32 metadata: kernel_sizes[0] in {7,9,11}; for int64 the
    // second 32-bit word is 0, for int32 it's kernel_sizes[1] (>=7).
    const bool is64 = (((const int*)KS)[1] == 0);

    // one warp <-> one conv; warps run independently (no further syncs)
    const int warp = threadIdx.x >> 5;
    const int c = blockIdx.x * CPB + warp;

    const int k = meta_at(KS, c, is64);
    const int d = meta_at(DS, c, is64);
    const int p = meta_at(PS, c, is64);
    const int L = N_IN + 2 * p - d * (k - 1);

    const float* wrow = W + c * KMAX;
    const float bias  = B[c];

    float mx; int neg;
    if (k == 7)       conv_feat_warp<7 >(xs, wrow, bias, d, p, L, mx, neg);
    else if (k == 9)  conv_feat_warp<9 >(xs, wrow, bias, d, p, L, mx, neg);
    else              conv_feat_warp<11>(xs, wrow, bias, d, p, L, mx, neg);

    mx  = warpReduceMax(mx);
    neg = warpReduceSum(neg);
    if ((threadIdx.x & 31) == 0) {
        const size_t base = (size_t)b * (2 * NCONV) + 2 * c;
        out[base]     = mx;
        out[base + 1] = (float)(L - neg) / (float)L;
    }
}

extern "C" void kernel_launch(void* const* d_in, const int* in_sizes, int n_in,
                              void* d_out, int out_size)
{
    const float* x  = (const float*)d_in[0];
    const float* W  = (const float*)d_in[1];
    const float* B  = (const float*)d_in[2];
    const void*  KS = d_in[3];
    const void*  DS = d_in[4];
    const void*  PS = d_in[5];
    float* out = (float*)d_out;

    const int batch = in_sizes[0] / N_IN;   // 256

    const size_t smem = (N_IN + 16) * sizeof(float);
    cudaFuncSetAttribute(feat_kernel,
                         cudaFuncAttributeMaxDynamicSharedMemorySize,
                         (int)smem);

    dim3 grid(NCONV / CPB, batch);
    feat_kernel<<<grid, TPB, smem>>>(x, W, B, KS, DS, PS, out);
}

// round 11
// speedup vs baseline: 1.0261x; 1.0261x over previous
#include <cuda_runtime.h>
#include <math_constants.h>

#define N_IN   16384
#define NCONV  128
#define KMAX   11
#define TPB    256
#define WPB    8     // warps per block; each warp processes 2 scheduled convs

__device__ int g_sched[NCONV];   // slot s owns convs g_sched[2s], g_sched[2s+1]

__device__ __forceinline__ float warpReduceMax(float v) {
#pragma unroll
    for (int o = 16; o > 0; o >>= 1)
        v = fmaxf(v, __shfl_xor_sync(0xffffffffu, v, o));
    return v;
}
__device__ __forceinline__ int warpReduceSum(int v) {
#pragma unroll
    for (int o = 16; o > 0; o >>= 1)
        v += __shfl_xor_sync(0xffffffffu, v, o);
    return v;
}

__device__ __forceinline__ int meta_at(const void* arr, int c, bool is64) {
    if (is64) return (int)((const long long*)arr)[c];
    return ((const int*)arr)[c];
}

// ---- schedule: rank convs by analytic cost, fold heavy+light into 64 slots ----
__global__ void sched_kernel(const void* __restrict__ KS,
                             const void* __restrict__ DS,
                             const void* __restrict__ PS)
{
    __shared__ float cost[NCONV];
    const int c = threadIdx.x;
    const bool is64 = (((const int*)KS)[1] == 0);
    const int k = meta_at(KS, c, is64);
    const int d = meta_at(DS, c, is64);
    const int p = meta_at(PS, c, is64);
    const int L = N_IN + 2 * p - d * (k - 1);
    const int nph = min(d, max(L, 1));
    cost[c] = (float)L * (float)(k + 5) + (float)nph * (float)(2 * k + 18);
    __syncthreads();

    int rank = 0;
    const float mc = cost[c];
    for (int j = 0; j < NCONV; j++) {
        const float cj = cost[j];
        rank += (cj > mc || (cj == mc && j < c)) ? 1 : 0;
    }
    const int idx = (rank < NCONV / 2) ? (2 * rank)
                                       : (2 * (NCONV - 1 - rank) + 1);
    g_sched[idx] = c;
}

// ---- ring FIR, no bounds checks. Loads exactly len+K-1 taps. ----
template <int K>
__device__ __forceinline__ void ring_fast(
    const float* __restrict__ xs, const float* __restrict__ w, float bias,
    int i0, int d, int len, float& mx, int& neg)
{
    const float* ptr = xs + i0;
    float z[K];
#pragma unroll
    for (int s = 0; s < K - 1; s++) { z[s] = *ptr; ptr += d; }

    const int full = len / K;
    const int rem  = len - full * K;

    for (int g = 0; g < full; g++) {
#pragma unroll
        for (int s = 0; s < K; s++) {
            z[(s + K - 1) % K] = *ptr; ptr += d;
            float y = fmaf(w[0], z[s % K], bias);
#pragma unroll
            for (int t = 1; t < K; t++)
                y = fmaf(w[t], z[(s + t) % K], y);
            mx = fmaxf(mx, y);
            neg += (int)(__float_as_uint(y) >> 31);
        }
    }
    // exact-length tail: oldest tap at z[0] (shift register)
#pragma unroll 1
    for (int s = 0; s < rem; s++) {
        float nw = *ptr; ptr += d;
        float y = fmaf(w[0], z[0], bias);
#pragma unroll
        for (int t = 1; t < K; t++)
            y = fmaf(w[t], (t < K - 1) ? z[t] : nw, y);
        mx = fmaxf(mx, y);
        neg += (int)(__float_as_uint(y) >> 31);
#pragma unroll
        for (int t = 0; t < K - 2; t++) z[t] = z[t + 1];
        z[K - 2] = nw;
    }
}

// ---- same ring, OOB taps clamped to zero sentinel xs[N_IN] ----
template <int K>
__device__ __forceinline__ void ring_clamped(
    const float* __restrict__ xs, const float* __restrict__ w, float bias,
    int i0, int d, int len, float& mx, int& neg)
{
    int ix = i0;
    float z[K];
#pragma unroll
    for (int s = 0; s < K - 1; s++) {
        unsigned ui = min((unsigned)ix, (unsigned)N_IN);
        z[s] = xs[ui]; ix += d;
    }

    const int full = len / K;
    const int rem  = len - full * K;

    for (int g = 0; g < full; g++) {
#pragma unroll
        for (int s = 0; s < K; s++) {
            unsigned ui = min((unsigned)ix, (unsigned)N_IN);
            z[(s + K - 1) % K] = xs[ui]; ix += d;
            float y = fmaf(w[0], z[s % K], bias);
#pragma unroll
            for (int t = 1; t < K; t++)
                y = fmaf(w[t], z[(s + t) % K], y);
            mx = fmaxf(mx, y);
            neg += (int)(__float_as_uint(y) >> 31);
        }
    }
#pragma unroll 1
    for (int s = 0; s < rem; s++) {
        unsigned ui = min((unsigned)ix, (unsigned)N_IN);
        float nw = xs[ui]; ix += d;
        float y = fmaf(w[0], z[0], bias);
#pragma unroll
        for (int t = 1; t < K; t++)
            y = fmaf(w[t], (t < K - 1) ? z[t] : nw, y);
        mx = fmaxf(mx, y);
        neg += (int)(__float_as_uint(y) >> 31);
#pragma unroll
        for (int t = 0; t < K - 2; t++) z[t] = z[t + 1];
        z[K - 2] = nw;
    }
}

// Segment [ma, mb) of phase r: clamped head | fast | clamped tail.
// If the fast portion is short (<2K), one clamped ring beats 3 preloads.
template <int K>
__device__ __forceinline__ void seg3(
    const float* __restrict__ xs, const float* __restrict__ w, float bias,
    int r, int d, int ma, int mb, int f_hi_p1, float& mx, int& neg)
{
    const int b1 = min(mb, max(ma, 0));
    const int b2 = max(b1, min(mb, f_hi_p1));
    if (b2 - b1 >= 2 * K) {
        if (ma < b1) ring_clamped<K>(xs, w, bias, r + ma * d, d, b1 - ma, mx, neg);
        ring_fast<K>(xs, w, bias, r + b1 * d, d, b2 - b1, mx, neg);
        if (b2 < mb) ring_clamped<K>(xs, w, bias, r + b2 * d, d, mb - b2, mx, neg);
    } else {
        ring_clamped<K>(xs, w, bias, r + ma * d, d, mb - ma, mx, neg);
    }
}

// One warp processes one conv. Outputs u = t - p = r + m*d.
template <int K>
__device__ __forceinline__ void conv_feat_warp(
    const float* __restrict__ xs,
    const float* __restrict__ wrow, float bias,
    int d, int p, int L,
    float& mx_out, int& neg_out)
{
    float w[K];
#pragma unroll
    for (int j = 0; j < K; j++) w[j] = wrow[j];

    float mx = -CUDART_INF_F;
    int   neg = 0;
    const int lane = threadIdx.x & 31;

    // Hoisted divides:
    //  m_lo(r) = -(pq + (prm + r >= d)); m_hi(r) = aq - (r > arm)
    //  f_hi(r) = nq - (r > nrm) - (K-1)   [last all-taps-in-range output]
    const int A   = L - 1 - p;
    const int pq  = p / d,          prm = p - pq * d;
    const int aq  = A / d,          arm = A - aq * d;
    const int nq  = (N_IN - 1) / d, nrm = (N_IN - 1) - nq * d;

    if (d >= 32) {
        for (int r = lane; r < d; r += 32) {
            const int m_lo = -(pq + ((prm + r) >= d ? 1 : 0));
            const int m_hi = aq - (r > arm ? 1 : 0);
            if (m_hi < m_lo) continue;
            const int f_hi = nq - (r > nrm ? 1 : 0) - (K - 1);
            seg3<K>(xs, w, bias, r, d, m_lo, m_hi + 1, f_hi + 1, mx, neg);
        }
    } else {
        const int nQ     = (32 + d - 1) / d;
        const int maxlen = (L + d - 1) / d;
        const int c0     = (maxlen + nQ - 1) / nQ;
        const int C      = (((c0 + 31) >> 5) << 5) | 1;  // >= c0, == 1 mod 32
        const int nItems = d * nQ;
        const float rd   = 1.0f / (float)d;

        for (int j = lane; j < nItems; j += 32) {
            int q = (int)((float)j * rd);
            int r = j - q * d;
            if (r < 0)       { r += d; q--; }
            else if (r >= d) { r -= d; q++; }

            const int m_lo = -(pq + ((prm + r) >= d ? 1 : 0));
            const int m_hi = aq - (r > arm ? 1 : 0);
            const int m0   = m_lo + q * C;
            const int m1   = min(m0 + C, m_hi + 1);
            if (m1 <= m0) continue;
            const int f_hi = nq - (r > nrm ? 1 : 0) - (K - 1);
            seg3<K>(xs, w, bias, r, d, m0, m1, f_hi + 1, mx, neg);
        }
    }

    mx_out = mx;
    neg_out = neg;
}

__global__ void __launch_bounds__(TPB, 3)
feat_kernel(const float* __restrict__ x,
            const float* __restrict__ W,
            const float* __restrict__ B,
            const void* __restrict__ KS,
            const void* __restrict__ DS,
            const void* __restrict__ PS,
            float* __restrict__ out)
{
    extern __shared__ float xs[];   // N_IN + zero sentinel
    const int b = blockIdx.y;

    {
        const float4* xr4 = (const float4*)(x + (size_t)b * N_IN);
        float4* xs4 = (float4*)xs;
        for (int i = threadIdx.x; i < N_IN / 4; i += TPB)
            xs4[i] = xr4[i];
        if (threadIdx.x == 0) xs[N_IN] = 0.0f;
    }
    __syncthreads();

    const bool is64 = (((const int*)KS)[1] == 0);

    // warp-slot from the balanced schedule; 2 convs per warp
    const int warp = threadIdx.x >> 5;
    const int slot = blockIdx.x * WPB + warp;

#pragma unroll 1
    for (int i = 0; i < 2; i++) {
        const int c = g_sched[2 * slot + i];
        const int k = meta_at(KS, c, is64);
        const int d = meta_at(DS, c, is64);
        const int p = meta_at(PS, c, is64);
        const int L = N_IN + 2 * p - d * (k - 1);

        const float* wrow = W + c * KMAX;
        const float bias  = B[c];

        float mx; int neg;
        if (k == 7)       conv_feat_warp<7 >(xs, wrow, bias, d, p, L, mx, neg);
        else if (k == 9)  conv_feat_warp<9 >(xs, wrow, bias, d, p, L, mx, neg);
        else              conv_feat_warp<11>(xs, wrow, bias, d, p, L, mx, neg);

        mx  = warpReduceMax(mx);
        neg = warpReduceSum(neg);
        if ((threadIdx.x & 31) == 0) {
            const size_t base = (size_t)b * (2 * NCONV) + 2 * c;
            out[base]     = mx;
            out[base + 1] = (float)(L - neg) / (float)L;
        }
    }
}

extern "C" void kernel_launch(void* const* d_in, const int* in_sizes, int n_in,
                              void* d_out, int out_size)
{
    const float* x  = (const float*)d_in[0];
    const float* W  = (const float*)d_in[1];
    const float* B  = (const float*)d_in[2];
    const void*  KS = d_in[3];
    const void*  DS = d_in[4];
    const void*  PS = d_in[5];
    float* out = (float*)d_out;

    const int batch = in_sizes[0] / N_IN;   // 256

    sched_kernel<<<1, NCONV>>>(KS, DS, PS);

    const size_t smem = (N_IN + 16) * sizeof(float);
    cudaFuncSetAttribute(feat_kernel,
                         cudaFuncAttributeMaxDynamicSharedMemorySize,
                         (int)smem);

    dim3 grid(NCONV / (2 * WPB), batch);   // (8, 256)
    feat_kernel<<<grid, TPB, smem>>>(x, W, B, KS, DS, PS, out);
}